// round 15
// baseline (speedup 1.0000x reference)
#include <cuda_runtime.h>
#include <cuda_bf16.h>
#include <math.h>
#include <stdint.h>

#define NSEQ  8192
#define VTOK  25
#define NROWS 204800          // NSEQ * VTOK
#define DM    256
#define NH    8
#define HD    32
#define DF    1024
#define N3    768
#define LDC   136             // pipelined A-chunk row stride (halves)
#define LDT   40              // attn per-head tile row stride (halves)
#define HSTR  3848            // attn per-head smem stride

// packed bf16 fragment weights (uint32 words): [tile][kb32][lane][uint4]
#define BQ_OFF 0
#define BP_OFF 98304
#define B1_OFF 131072
#define B2_OFF 262144
#define WU32   393216

__device__ uint32_t       g_wb[WU32];
__device__ __nv_bfloat16  g_qkvh[(size_t)NROWS * N3];   // q-hat / k-hat / v (bf16)
__device__ __nv_bfloat16  g_att[(size_t)NROWS * DM];    // attention out
__device__ float          g_xf [(size_t)NROWS * DM];    // residual after proj (fp32)
__device__ __nv_bfloat16  g_h  [(size_t)NROWS * DF];    // FFN hidden

__device__ __forceinline__ float gelu_exact(float v) {
    return 0.5f * v * (1.f + erff(v * 0.70710678118654752440f));
}
__device__ __forceinline__ uint32_t pack_bf2(float lo, float hi) {
    __nv_bfloat162 p;
    p.x = __float2bfloat16_rn(lo);
    p.y = __float2bfloat16_rn(hi);
    return *(uint32_t*)&p;
}

// ---- weight packing to bf16 m16n8k16 B-fragments ----
__global__ void prep_pack(const float* __restrict__ qkv_w, const float* __restrict__ proj_w,
                          const float* __restrict__ f1,    const float* __restrict__ f2) {
    int i = blockIdx.x * 256 + threadIdx.x;
    if (i >= WU32) return;
    int comp = i & 3, lane = (i >> 2) & 31;
    int g = lane >> 2, t4 = lane & 3;
    int klo = 2 * t4 + ((comp & 1) << 3) + ((comp >> 1) << 4);
    const float* W; int ldw, k, col;
    if (i < BP_OFF) {                         // QKV: 96 tiles x 8 kb
        int r2 = i >> 7;  int kb = r2 & 7, tile = r2 >> 3;
        col = tile * 8 + g; k = kb * 32 + klo; W = qkv_w; ldw = N3;
    } else if (i < B1_OFF) {                  // proj: 32 tiles x 8 kb
        int r2 = (i - BP_OFF) >> 7;  int kb = r2 & 7, tile = r2 >> 3;
        col = tile * 8 + g; k = kb * 32 + klo; W = proj_w; ldw = DM;
    } else if (i < B2_OFF) {                  // ffn1: 128 tiles x 8 kb
        int r2 = (i - B1_OFF) >> 7;  int kb = r2 & 7, tile = r2 >> 3;
        col = tile * 8 + g; k = kb * 32 + klo; W = f1; ldw = DF;
    } else {                                  // ffn2: 32 tiles x 32 kb (K=1024)
        int r2 = (i - B2_OFF) >> 7;  int kb = r2 & 31, tile = r2 >> 5;
        col = tile * 8 + g; k = kb * 32 + klo; W = f2; ldw = DM;
    }
    g_wb[i] = pack_bf2(W[(size_t)k * ldw + col], W[(size_t)(k + 1) * ldw + col]);
}

#define MMA_BF(D, A, B0, B1)                                                \
    asm("mma.sync.aligned.m16n8k16.row.col.f32.bf16.bf16.f32 "              \
        "{%0,%1,%2,%3}, {%4,%5,%6,%7}, {%8,%9}, {%0,%1,%2,%3};"             \
        : "+f"(D[0]), "+f"(D[1]), "+f"(D[2]), "+f"(D[3])                    \
        : "r"(A[0]), "r"(A[1]), "r"(A[2]), "r"(A[3]), "r"(B0), "r"(B1))

#define LDSM4(A, addr)                                                      \
    asm volatile("ldmatrix.sync.aligned.m8n8.x4.shared.b16 {%0,%1,%2,%3}, [%4];" \
        : "=r"(A[0]), "=r"(A[1]), "=r"(A[2]), "=r"(A[3]) : "r"(addr))

#define LDSM4T(A, addr)                                                     \
    asm volatile("ldmatrix.sync.aligned.m8n8.x4.trans.shared.b16 {%0,%1,%2,%3}, [%4];" \
        : "=r"(A[0]), "=r"(A[1]), "=r"(A[2]), "=r"(A[3]) : "r"(addr))

#define LDS128U(r0, r1, r2, r3, addr)                                       \
    asm volatile("ld.shared.v4.u32 {%0,%1,%2,%3}, [%4];"                    \
        : "=r"(r0), "=r"(r1), "=r"(r2), "=r"(r3) : "r"(addr))

__device__ __forceinline__ void cp_async16(uint32_t saddr, const void* g) {
    asm volatile("cp.async.cg.shared.global [%0], [%1], 16;" :: "r"(saddr), "l"(g) : "memory");
}
#define CP_COMMIT() asm volatile("cp.async.commit_group;" ::: "memory")
#define CP_WAIT0()  asm volatile("cp.async.wait_group 0;" ::: "memory")
#define CP_WAIT1()  asm volatile("cp.async.wait_group 1;" ::: "memory")

__device__ __forceinline__ uint32_t ldsm_addr(const __nv_bfloat16* base, int ldh, int lane) {
    return (uint32_t)__cvta_generic_to_shared(base + (lane & 15) * ldh + (lane >> 4) * 8);
}

// Warp computes 32 x NT*8 tile for one K-chunk; A via ldmatrix, B frags from smem.
template<int NT, int KB>
__device__ __forceinline__ void gemm_sm(uint32_t a0addr, uint32_t a1addr,
                                        uint32_t sBaddr, int tbase,
                                        float (&acc)[2][NT][4], int lane)
{
    #pragma unroll
    for (int kb = 0; kb < KB; kb++) {
        uint32_t A0[4], A1[4], A2[4], A3[4];
        LDSM4(A0, a0addr + kb * 64);
        LDSM4(A1, a1addr + kb * 64);
        LDSM4(A2, a0addr + kb * 64 + 32);
        LDSM4(A3, a1addr + kb * 64 + 32);
        #pragma unroll
        for (int nt = 0; nt < NT; nt++) {
            uint32_t b0, b1, b2, b3;
            LDS128U(b0, b1, b2, b3, sBaddr + (((tbase + nt) * KB + kb) * 32 + lane) * 16);
            MMA_BF(acc[0][nt], A0, b0, b1);
            MMA_BF(acc[1][nt], A1, b0, b1);
            MMA_BF(acc[0][nt], A2, b2, b3);
            MMA_BF(acc[1][nt], A3, b2, b3);
        }
    }
}

// ---- chunk loaders ----
__device__ __forceinline__ void load_chunkA(const __nv_bfloat16* __restrict__ Ag,
                                            size_t row0, int srow, int c,
                                            __nv_bfloat16* __restrict__ sAbuf, int tid)
{
    uint32_t sbase = (uint32_t)__cvta_generic_to_shared(sAbuf);
    #pragma unroll
    for (int i = 0; i < 8; i++) {
        int idx = tid + i * 256;
        int row = idx >> 4, c16 = idx & 15;
        cp_async16(sbase + (row * LDC + c16 * 8) * 2,
                   Ag + (row0 + row) * (size_t)srow + c * 128 + c16 * 8);
    }
}
template<int KBT>
__device__ __forceinline__ void load_chunkB(const uint4* __restrict__ Bbase, int c,
                                            uint32_t sBbuf, int tid)
{
    #pragma unroll
    for (int i = 0; i < 4; i++) {
        int idx = tid + i * 256;
        int t = idx >> 7, rem = idx & 127, kb = rem >> 5, ln = rem & 31;
        cp_async16(sBbuf + idx * 16,
                   Bbase + ((size_t)(t * KBT + c * 4 + kb) * 32 + ln));
    }
}

// ---- LN row: fp32 global row -> bf16 into two A-chunk buffers ----
__device__ __forceinline__ void ln_row_2chunk(const float* __restrict__ src,
                                              __nv_bfloat16* __restrict__ d0,
                                              __nv_bfloat16* __restrict__ d1,
                                              const float* __restrict__ gg,
                                              const float* __restrict__ bb, int lane)
{
    float v[8], s = 0.f, s2 = 0.f;
    #pragma unroll
    for (int j = 0; j < 8; j++) { v[j] = src[lane + 32 * j]; s += v[j]; s2 += v[j] * v[j]; }
    #pragma unroll
    for (int o = 16; o > 0; o >>= 1) {
        s  += __shfl_xor_sync(0xffffffffu, s,  o);
        s2 += __shfl_xor_sync(0xffffffffu, s2, o);
    }
    float mean = s * (1.f / DM);
    float var  = s2 * (1.f / DM) - mean * mean;
    float inv  = rsqrtf(var + 1e-5f);
    #pragma unroll
    for (int j = 0; j < 8; j++) {
        int c = lane + 32 * j;
        __nv_bfloat16 r = __float2bfloat16_rn((v[j] - mean) * inv * gg[c] + bb[c]);
        if (j < 4) d0[c] = r; else d1[c - 128] = r;
    }
}

#define SM_PIPE 102400    // 2*(128*LDC*2) + 2*16384

#define GEMM_PRO()                                                          \
    extern __shared__ __nv_bfloat16 sA[];                                   \
    uint32_t sB0 = (uint32_t)__cvta_generic_to_shared(sA) + 2 * 128 * LDC * 2; \
    const int tid = threadIdx.x, lane = tid & 31;                           \
    const int wid = tid >> 5, wm = wid >> 1, wn = wid & 1;                  \
    const int g = lane >> 2, t4 = lane & 3;                                 \
    const int ntblk = blockIdx.x;                                           \
    const size_t mb = (size_t)blockIdx.y * 128;                             \
    float acc[2][4][4];                                                     \
    _Pragma("unroll") for (int mt = 0; mt < 2; mt++)                        \
    _Pragma("unroll") for (int nt = 0; nt < 4; nt++)                        \
    _Pragma("unroll") for (int e = 0; e < 4; e++) acc[mt][nt][e] = 0.f;

// ---- pipelined mainloop for bf16-A sources (proj, ffn2) ----
template<int KC, int KBT>
__device__ __forceinline__ void gemm_pipe(const __nv_bfloat16* __restrict__ Ag,
                                          size_t mb, int srow,
                                          const uint4* __restrict__ Bbase,
                                          float (&acc)[2][4][4],
                                          __nv_bfloat16* sA, uint32_t sB0,
                                          int tid, int lane, int wm, int wn)
{
    __nv_bfloat16* sA0 = sA;
    __nv_bfloat16* sA1 = sA + 128 * LDC;
    load_chunkA(Ag, mb, srow, 0, sA0, tid);
    load_chunkB<KBT>(Bbase, 0, sB0, tid);
    CP_COMMIT();
    load_chunkA(Ag, mb, srow, 1, sA1, tid);
    load_chunkB<KBT>(Bbase, 1, sB0 + 16384, tid);
    CP_COMMIT();
    #pragma unroll
    for (int c = 0; c < KC; c++) {
        if (c < KC - 1) { CP_WAIT1(); } else { CP_WAIT0(); }
        __syncthreads();
        __nv_bfloat16* sAc = (c & 1) ? sA1 : sA0;
        uint32_t sBc = (c & 1) ? (sB0 + 16384) : sB0;
        uint32_t a0 = ldsm_addr(sAc + wm * 32 * LDC, LDC, lane);
        uint32_t a1 = a0 + 16 * LDC * 2;
        gemm_sm<4, 4>(a0, a1, sBc, wn * 4, acc, lane);
        if (c + 2 < KC) {
            __syncthreads();
            load_chunkA(Ag, mb, srow, c + 2, sAc, tid);
            load_chunkB<KBT>(Bbase, c + 2, sBc, tid);
            CP_COMMIT();
        }
    }
}

// ---- mainloop with fused LayerNorm A (K = 256 = 2 chunks, A static) ----
template<int KBT>
__device__ __forceinline__ void gemm_pipe_ln(const float* __restrict__ src,
                                             size_t mb,
                                             const float* __restrict__ gg,
                                             const float* __restrict__ bbln,
                                             const uint4* __restrict__ Bbase,
                                             float (&acc)[2][4][4],
                                             __nv_bfloat16* sA, uint32_t sB0,
                                             int tid, int lane, int wm, int wn)
{
    __nv_bfloat16* sA0 = sA;
    __nv_bfloat16* sA1 = sA + 128 * LDC;
    load_chunkB<KBT>(Bbase, 0, sB0, tid);
    CP_COMMIT();
    load_chunkB<KBT>(Bbase, 1, sB0 + 16384, tid);
    CP_COMMIT();
    // LN A tile (overlaps B cp.asyncs): warp per row
    const int wid = tid >> 5;
    #pragma unroll
    for (int rr = 0; rr < 16; rr++) {
        int r = wid + rr * 8;
        ln_row_2chunk(src + (mb + r) * DM, sA0 + r * LDC, sA1 + r * LDC, gg, bbln, lane);
    }
    CP_WAIT1();
    __syncthreads();
    {
        uint32_t a0 = ldsm_addr(sA0 + wm * 32 * LDC, LDC, lane);
        gemm_sm<4, 4>(a0, a0 + 16 * LDC * 2, sB0, wn * 4, acc, lane);
    }
    CP_WAIT0();
    __syncthreads();
    {
        uint32_t a0 = ldsm_addr(sA1 + wm * 32 * LDC, LDC, lane);
        gemm_sm<4, 4>(a0, a0 + 16 * LDC * 2, sB0 + 16384, wn * 4, acc, lane);
    }
}

// ---- QKV: LN1(x) @ qkv_w + b, fused q/k L2-norm -> g_qkvh. grid (12, 1600) ----
__global__ __launch_bounds__(256, 2) void k_qkv(const float* __restrict__ x,
                                                const float* __restrict__ ln1_g,
                                                const float* __restrict__ ln1_b,
                                                const float* __restrict__ bias,
                                                const float* __restrict__ lscale)
{
    GEMM_PRO();
    gemm_pipe_ln<8>(x, mb, ln1_g, ln1_b,
                    (const uint4*)g_wb + BQ_OFF / 4 + (size_t)ntblk * 2048,
                    acc, sA, sB0, tid, lane, wm, wn);

    const int cb = ntblk * 64 + wn * 32;
    const bool donorm = (ntblk < 8);
    float qmul = 1.f;
    if (ntblk < 4)
        qmul = expf(fminf(lscale[(cb & 255) >> 5], 4.6051701859880913680f))
             * 0.17677669529663688110f;     // sc_h / sqrt(32)

    float bv[8];
    #pragma unroll
    for (int nt = 0; nt < 4; nt++) {
        bv[2 * nt]     = bias[cb + nt * 8 + 2 * t4];
        bv[2 * nt + 1] = bias[cb + nt * 8 + 2 * t4 + 1];
    }

    #pragma unroll
    for (int mt = 0; mt < 2; mt++)
        #pragma unroll
        for (int hrow = 0; hrow < 2; hrow++) {
            float v[8];
            #pragma unroll
            for (int nt = 0; nt < 4; nt++) {
                v[2 * nt]     = acc[mt][nt][2 * hrow]     + bv[2 * nt];
                v[2 * nt + 1] = acc[mt][nt][2 * hrow + 1] + bv[2 * nt + 1];
            }
            float s = qmul;
            if (donorm) {
                float ssq = 0.f;
                #pragma unroll
                for (int e = 0; e < 8; e++) ssq = fmaf(v[e], v[e], ssq);
                ssq += __shfl_xor_sync(0xffffffffu, ssq, 1);
                ssq += __shfl_xor_sync(0xffffffffu, ssq, 2);
                s = qmul / fmaxf(sqrtf(ssq), 1e-12f);
            }
            size_t R = mb + wm * 32 + mt * 16 + g + hrow * 8;
            #pragma unroll
            for (int nt = 0; nt < 4; nt++)
                *(uint32_t*)(g_qkvh + R * N3 + cb + nt * 8 + 2 * t4) =
                    pack_bf2(v[2 * nt] * s, v[2 * nt + 1] * s);
        }
}

// ---- attention: block = sequence, warp = head; pure MMA ----
__global__ __launch_bounds__(256, 2) void attn_kernel()
{
    extern __shared__ __nv_bfloat16 smt[];
    const int tid = threadIdx.x, lane = tid & 31, h = tid >> 5;
    const int g = lane >> 2, t4 = lane & 3;
    const size_t seq = blockIdx.x;

    const uint4* src = (const uint4*)(g_qkvh + seq * (size_t)(VTOK * N3));
    #pragma unroll
    for (int it = 0; it < 10; it++) {
        int idx = tid + it * 256;
        if (idx < 2400) {
            int row = idx / 96, c8 = idx - row * 96;
            int col = c8 * 8;
            int region = col >> 8;              // 0=q 1=k 2=v
            int head = (col & 255) >> 5;
            *(uint4*)(smt + head * HSTR + region * (32 * LDT) + row * LDT + (col & 31)) = src[idx];
        }
    }
    if (tid < 224) {
        int head = tid / 28, i2 = tid % 28;
        uint4 z = make_uint4(0, 0, 0, 0);
        *(uint4*)(smt + head * HSTR + 2 * (32 * LDT) + (25 + (i2 >> 2)) * LDT + (i2 & 3) * 8) = z;
    }
    __syncthreads();

    __nv_bfloat16* sq = smt + h * HSTR;
    __nv_bfloat16* sk = sq + 32 * LDT;
    __nv_bfloat16* sv = sk + 32 * LDT;

    uint32_t qb  = (uint32_t)__cvta_generic_to_shared(sq);
    uint32_t kbb = (uint32_t)__cvta_generic_to_shared(sk);
    uint32_t vbb = (uint32_t)__cvta_generic_to_shared(sv);

    uint32_t aq[2][2][4];
    #pragma unroll
    for (int mt = 0; mt < 2; mt++)
        #pragma unroll
        for (int c = 0; c < 2; c++) {
            uint32_t addr = qb + (mt * 16 + (lane & 15)) * (LDT * 2) + (lane >> 4) * 16 + c * 32;
            LDSM4(aq[mt][c], addr);
        }
    uint32_t bk[4][4];
    #pragma unroll
    for (int nt = 0; nt < 4; nt++) {
        uint32_t addr = kbb + (nt * 8 + (lane & 7)) * (LDT * 2) + (lane >> 3) * 16;
        LDSM4(bk[nt], addr);
    }

    float accl[2][4][4];
    #pragma unroll
    for (int mt = 0; mt < 2; mt++)
        #pragma unroll
        for (int nt = 0; nt < 4; nt++)
            #pragma unroll
            for (int e = 0; e < 4; e++) accl[mt][nt][e] = 0.f;
    #pragma unroll
    for (int mt = 0; mt < 2; mt++)
        #pragma unroll
        for (int nt = 0; nt < 4; nt++) {
            MMA_BF(accl[mt][nt], aq[mt][0], bk[nt][0], bk[nt][1]);
            MMA_BF(accl[mt][nt], aq[mt][1], bk[nt][2], bk[nt][3]);
        }

    #pragma unroll
    for (int mt = 0; mt < 2; mt++)
        #pragma unroll
        for (int hrow = 0; hrow < 2; hrow++) {
            float m = -1e30f;
            #pragma unroll
            for (int nt = 0; nt < 4; nt++)
                #pragma unroll
                for (int e = 0; e < 2; e++) {
                    int c = nt * 8 + 2 * t4 + e;
                    float vl = (c < VTOK) ? accl[mt][nt][2 * hrow + e] : -1e30f;
                    accl[mt][nt][2 * hrow + e] = vl;
                    m = fmaxf(m, vl);
                }
            m = fmaxf(m, __shfl_xor_sync(0xffffffffu, m, 1));
            m = fmaxf(m, __shfl_xor_sync(0xffffffffu, m, 2));
            float s = 0.f;
            #pragma unroll
            for (int nt = 0; nt < 4; nt++)
                #pragma unroll
                for (int e = 0; e < 2; e++) {
                    float p = __expf(accl[mt][nt][2 * hrow + e] - m);
                    accl[mt][nt][2 * hrow + e] = p;
                    s += p;
                }
            s += __shfl_xor_sync(0xffffffffu, s, 1);
            s += __shfl_xor_sync(0xffffffffu, s, 2);
            float rs = 1.f / s;
            #pragma unroll
            for (int nt = 0; nt < 4; nt++)
                #pragma unroll
                for (int e = 0; e < 2; e++) accl[mt][nt][2 * hrow + e] *= rs;
        }

    uint32_t pa[2][2][4];
    #pragma unroll
    for (int mt = 0; mt < 2; mt++)
        #pragma unroll
        for (int c = 0; c < 2; c++) {
            pa[mt][c][0] = pack_bf2(accl[mt][2*c  ][0], accl[mt][2*c  ][1]);
            pa[mt][c][1] = pack_bf2(accl[mt][2*c  ][2], accl[mt][2*c  ][3]);
            pa[mt][c][2] = pack_bf2(accl[mt][2*c+1][0], accl[mt][2*c+1][1]);
            pa[mt][c][3] = pack_bf2(accl[mt][2*c+1][2], accl[mt][2*c+1][3]);
        }

    uint32_t bv[2][2][4];
    #pragma unroll
    for (int c = 0; c < 2; c++)
        #pragma unroll
        for (int np = 0; np < 2; np++) {
            uint32_t addr = vbb + (c * 16 + ((lane >> 3) & 1) * 8 + (lane & 7)) * (LDT * 2)
                          + np * 32 + (lane >> 4) * 16;
            LDSM4T(bv[c][np], addr);
        }

    float acco[2][4][4];
    #pragma unroll
    for (int mt = 0; mt < 2; mt++)
        #pragma unroll
        for (int nt = 0; nt < 4; nt++)
            #pragma unroll
            for (int e = 0; e < 4; e++) acco[mt][nt][e] = 0.f;
    #pragma unroll
    for (int mt = 0; mt < 2; mt++)
        #pragma unroll
        for (int nt = 0; nt < 4; nt++) {
            int np = nt >> 1, hi = (nt & 1) * 2;
            MMA_BF(acco[mt][nt], pa[mt][0], bv[0][np][hi], bv[0][np][hi + 1]);
            MMA_BF(acco[mt][nt], pa[mt][1], bv[1][np][hi], bv[1][np][hi + 1]);
        }

    #pragma unroll
    for (int mt = 0; mt < 2; mt++)
        #pragma unroll
        for (int hrow = 0; hrow < 2; hrow++) {
            int token = mt * 16 + g + hrow * 8;
            if (token < VTOK) {
                __nv_bfloat16* og = g_att + (seq * VTOK + token) * DM + h * HD;
                #pragma unroll
                for (int nt = 0; nt < 4; nt++)
                    *(uint32_t*)(og + nt * 8 + 2 * t4) =
                        pack_bf2(acco[mt][nt][2 * hrow], acco[mt][nt][2 * hrow + 1]);
            }
        }
}

// ---- proj GEMM + residual -> g_xf (fp32). grid (4, 1600) ----
__global__ __launch_bounds__(256, 2) void k_proj(const float* __restrict__ x,
                                                 const float* __restrict__ bias)
{
    GEMM_PRO();
    gemm_pipe<2, 8>(g_att, mb, DM, (const uint4*)g_wb + BP_OFF / 4 + (size_t)ntblk * 2048,
                    acc, sA, sB0, tid, lane, wm, wn);
    const int cb = ntblk * 64 + wn * 32;
    #pragma unroll
    for (int mt = 0; mt < 2; mt++)
        #pragma unroll
        for (int nt = 0; nt < 4; nt++) {
            int c = cb + nt * 8 + 2 * t4;
            float b0 = bias[c], b1 = bias[c + 1];
            #pragma unroll
            for (int hrow = 0; hrow < 2; hrow++) {
                size_t R = mb + wm * 32 + mt * 16 + g + hrow * 8;
                float2 xv = *(const float2*)(x + R * DM + c);
                float2 o;
                o.x = xv.x + acc[mt][nt][2 * hrow]     + b0;
                o.y = xv.y + acc[mt][nt][2 * hrow + 1] + b1;
                *(float2*)(g_xf + R * DM + c) = o;
            }
        }
}

// ---- FFN1: LN2(g_xf) @ ffn_w1 + b, gelu -> g_h (bf16). grid (16, 1600) ----
__global__ __launch_bounds__(256, 2) void k_ffn1(const float* __restrict__ ln2_g,
                                                 const float* __restrict__ ln2_b,
                                                 const float* __restrict__ bias)
{
    GEMM_PRO();
    gemm_pipe_ln<8>(g_xf, mb, ln2_g, ln2_b,
                    (const uint4*)g_wb + B1_OFF / 4 + (size_t)ntblk * 2048,
                    acc, sA, sB0, tid, lane, wm, wn);
    const int cb = ntblk * 64 + wn * 32;
    #pragma unroll
    for (int mt = 0; mt < 2; mt++)
        #pragma unroll
        for (int nt = 0; nt < 4; nt++) {
            int c = cb + nt * 8 + 2 * t4;
            float b0 = bias[c], b1 = bias[c + 1];
            #pragma unroll
            for (int hrow = 0; hrow < 2; hrow++) {
                size_t R = mb + wm * 32 + mt * 16 + g + hrow * 8;
                *(uint32_t*)(g_h + R * DF + c) =
                    pack_bf2(gelu_exact(acc[mt][nt][2 * hrow] + b0),
                             gelu_exact(acc[mt][nt][2 * hrow + 1] + b1));
            }
        }
}

// ---- FFN2 GEMM + residual -> out (fp32). grid (4, 1600) ----
__global__ __launch_bounds__(256, 2) void k_ffn2(const float* __restrict__ bias,
                                                 float* __restrict__ out)
{
    GEMM_PRO();
    gemm_pipe<8, 32>(g_h, mb, DF, (const uint4*)g_wb + B2_OFF / 4 + (size_t)ntblk * 8192,
                     acc, sA, sB0, tid, lane, wm, wn);
    const int cb = ntblk * 64 + wn * 32;
    #pragma unroll
    for (int mt = 0; mt < 2; mt++)
        #pragma unroll
        for (int nt = 0; nt < 4; nt++) {
            int c = cb + nt * 8 + 2 * t4;
            float b0 = bias[c], b1 = bias[c + 1];
            #pragma unroll
            for (int hrow = 0; hrow < 2; hrow++) {
                size_t R = mb + wm * 32 + mt * 16 + g + hrow * 8;
                float2 xv = *(const float2*)(g_xf + R * DM + c);
                float2 o;
                o.x = xv.x + acc[mt][nt][2 * hrow]     + b0;
                o.y = xv.y + acc[mt][nt][2 * hrow + 1] + b1;
                *(float2*)(out + R * DM + c) = o;
            }
        }
}

extern "C" void kernel_launch(void* const* d_in, const int* in_sizes, int n_in,
                              void* d_out, int out_size)
{
    const float* x      = (const float*)d_in[0];
    const float* ln1_g  = (const float*)d_in[1];
    const float* ln1_b  = (const float*)d_in[2];
    const float* qkv_w  = (const float*)d_in[3];
    const float* qkv_b  = (const float*)d_in[4];
    const float* proj_w = (const float*)d_in[5];
    const float* proj_b = (const float*)d_in[6];
    const float* lscale = (const float*)d_in[7];
    const float* ln2_g  = (const float*)d_in[8];
    const float* ln2_b  = (const float*)d_in[9];
    const float* ffn_w1 = (const float*)d_in[10];
    const float* ffn_b1 = (const float*)d_in[11];
    const float* ffn_w2 = (const float*)d_in[12];
    const float* ffn_b2 = (const float*)d_in[13];
    float* out = (float*)d_out;

    const int smQ = 8 * HSTR * 2;                   // 61568 (attn tiles)
    cudaFuncSetAttribute(k_qkv,  cudaFuncAttributeMaxDynamicSharedMemorySize, SM_PIPE);
    cudaFuncSetAttribute(k_proj, cudaFuncAttributeMaxDynamicSharedMemorySize, SM_PIPE);
    cudaFuncSetAttribute(k_ffn1, cudaFuncAttributeMaxDynamicSharedMemorySize, SM_PIPE);
    cudaFuncSetAttribute(k_ffn2, cudaFuncAttributeMaxDynamicSharedMemorySize, SM_PIPE);
    cudaFuncSetAttribute(attn_kernel, cudaFuncAttributeMaxDynamicSharedMemorySize, smQ);

    prep_pack<<<(WU32 + 255) / 256, 256>>>(qkv_w, proj_w, ffn_w1, ffn_w2);
    k_qkv <<<dim3(12, 1600), 256, SM_PIPE>>>(x, ln1_g, ln1_b, qkv_b, lscale);
    attn_kernel<<<NSEQ, 256, smQ>>>();
    k_proj<<<dim3(4, 1600), 256, SM_PIPE>>>(x, proj_b);
    k_ffn1<<<dim3(16, 1600), 256, SM_PIPE>>>(ln2_g, ln2_b, ffn_b1);
    k_ffn2<<<dim3(4, 1600), 256, SM_PIPE>>>(ffn_b2, out);
}